// round 1
// baseline (speedup 1.0000x reference)
#include <cuda_runtime.h>

namespace {

constexpr int NQ     = 12;
constexpr int DEPTH  = 6;
constexpr int NSTATE = 1 << NQ;        // 4096
constexpr int NT     = 256;            // threads per CTA
constexpr int PT     = NSTATE / NT;    // 16 amplitudes per thread
constexpr int NPAIRS = NSTATE / 2;     // 2048

struct C { float re, im; };

__device__ __forceinline__ C cmul(C a, C b) {
    return { a.re * b.re - a.im * b.im, a.re * b.im + a.im * b.re };
}
// a*b (fma form)
__device__ __forceinline__ C cmuln(C a, C b) {
    return { fmaf(a.re, b.re, -(a.im * b.im)), fmaf(a.re, b.im, a.im * b.re) };
}
// acc + a*b
__device__ __forceinline__ C cmadd(C a, C b, C acc) {
    return { fmaf(a.re, b.re, fmaf(-a.im, b.im, acc.re)),
             fmaf(a.re, b.im, fmaf(a.im, b.re, acc.im)) };
}

__global__ void __launch_bounds__(NT) qsim_kernel(const float* __restrict__ x,
                                                  const float* __restrict__ params,
                                                  float* __restrict__ out)
{
    __shared__ float sRe[NSTATE];
    __shared__ float sIm[NSTATE];
    __shared__ C     sU[DEPTH][NQ][4];      // fused 2x2 per (layer, qubit)
    __shared__ float sRed[NT / 32][NQ];

    const int t = threadIdx.x;
    const int b = blockIdx.x;

    // ---- Build fused rotation matrices: U = RX(g) @ RZ(b) @ RY(a) ----
    // Layer 0 additionally absorbs the input-encoding RX: U0 = U @ RX(x_i).
    if (t < DEPTH * NQ) {
        const int d = t / NQ, i = t % NQ;
        const float* pp = params + (d * NQ + i) * 3;
        float sa, ca, sb, cb, sg, cg;
        sincosf(0.5f * pp[0], &sa, &ca);
        sincosf(0.5f * pp[1], &sb, &cb);
        sincosf(0.5f * pp[2], &sg, &cg);
        // M1 = RZ(beta) @ RY(alpha):
        //   row0 = e^{-i b/2} * [ca, -sa], row1 = e^{+i b/2} * [sa, ca]
        C m00 = {  cb * ca, -sb * ca };
        C m01 = { -cb * sa,  sb * sa };
        C m10 = {  cb * sa,  sb * sa };
        C m11 = {  cb * ca,  sb * ca };
        // U = RX(gamma) @ M1, RX = [[cg, -i sg], [-i sg, cg]],  (-i)*z = (z.im, -z.re)
        C u00 = { cg * m00.re + sg * m10.im, cg * m00.im - sg * m10.re };
        C u01 = { cg * m01.re + sg * m11.im, cg * m01.im - sg * m11.re };
        C u10 = { sg * m00.im + cg * m10.re, -sg * m00.re + cg * m10.im };
        C u11 = { sg * m01.im + cg * m11.re, -sg * m01.re + cg * m11.im };
        if (d == 0) {
            float sx, cx;
            sincosf(0.5f * x[b * NQ + i], &sx, &cx);
            // U' = U @ RX(x): col0' = cx*col0 + (-i sx)*col1 ; col1' = (-i sx)*col0 + cx*col1
            C v00 = { cx * u00.re + sx * u01.im,  cx * u00.im - sx * u01.re };
            C v01 = { sx * u00.im + cx * u01.re, -sx * u00.re + cx * u01.im };
            C v10 = { cx * u10.re + sx * u11.im,  cx * u10.im - sx * u11.re };
            C v11 = { sx * u10.im + cx * u11.re, -sx * u10.re + cx * u11.im };
            u00 = v00; u01 = v01; u10 = v10; u11 = v11;
        }
        sU[d][i][0] = u00; sU[d][i][1] = u01; sU[d][i][2] = u10; sU[d][i][3] = u11;
    }
    __syncthreads();

    // ---- Layer 0 applied to |0..0> is a product state: amp(idx) = prod_i U0[i][bit_i][0] ----
    {
        // wires 4..11 live in bits 7..0 of t (fixed per thread)
        C plo = { 1.f, 0.f };
        #pragma unroll
        for (int i = 4; i < NQ; ++i) {
            int bit = (t >> (11 - i)) & 1;
            plo = cmul(plo, sU[0][i][bit ? 2 : 0]);   // row bit, col 0
        }
        #pragma unroll
        for (int r = 0; r < PT; ++r) {
            int idx = t + NT * r;                     // bits 8..11 of idx == r
            C phi = { 1.f, 0.f };
            #pragma unroll
            for (int i = 0; i < 4; ++i) {
                int bit = (idx >> (11 - i)) & 1;
                phi = cmul(phi, sU[0][i][bit ? 2 : 0]);
            }
            C amp = cmul(phi, plo);
            sRe[idx] = amp.re; sIm[idx] = amp.im;
        }
    }
    __syncthreads();

    // Circuit: for each layer, (gates already applied for d=0) then CNOT chain,
    // then 12 fused gates for d=1..5 each followed by the chain.
    for (int d = 0; d < DEPTH; ++d) {
        if (d > 0) {
            #pragma unroll
            for (int i = 0; i < NQ; ++i) {
                const int p = 11 - i;                 // integer bit position of wire i
                const C u00 = sU[d][i][0], u01 = sU[d][i][1];
                const C u10 = sU[d][i][2], u11 = sU[d][i][3];
                const int lowmask = (1 << p) - 1;
                #pragma unroll
                for (int j = t; j < NPAIRS; j += NT) {
                    int i0 = ((j & ~lowmask) << 1) | (j & lowmask);
                    int i1 = i0 | (1 << p);
                    C a = { sRe[i0], sIm[i0] };
                    C c = { sRe[i1], sIm[i1] };
                    C na = cmadd(u01, c, cmuln(u00, a));
                    C nb = cmadd(u11, c, cmuln(u10, a));
                    sRe[i0] = na.re; sIm[i0] = na.im;
                    sRe[i1] = nb.re; sIm[i1] = nb.im;
                }
                __syncthreads();
            }
        }
        // CNOT chain (adjacent, c=0..10) == Gray-code gather: state'[i] = state[i ^ (i>>1)]
        {
            float tr[PT], ti[PT];
            #pragma unroll
            for (int r = 0; r < PT; ++r) {
                int idx = t + NT * r;
                int src = idx ^ (idx >> 1);
                tr[r] = sRe[src]; ti[r] = sIm[src];
            }
            __syncthreads();
            #pragma unroll
            for (int r = 0; r < PT; ++r) {
                int idx = t + NT * r;
                sRe[idx] = tr[r]; sIm[idx] = ti[r];
            }
            __syncthreads();
        }
    }

    // ---- Pauli-Z expvals: out[k] = sum_idx (1 - 2*bit_k(idx)) * |amp|^2 ----
    float acc[NQ];
    #pragma unroll
    for (int k = 0; k < NQ; ++k) acc[k] = 0.f;
    #pragma unroll
    for (int r = 0; r < PT; ++r) {
        int idx = t + NT * r;
        float re = sRe[idx], im = sIm[idx];
        float pr = re * re + im * im;
        #pragma unroll
        for (int k = 0; k < NQ; ++k)
            acc[k] += ((idx >> (11 - k)) & 1) ? -pr : pr;
    }
    #pragma unroll
    for (int k = 0; k < NQ; ++k) {
        #pragma unroll
        for (int off = 16; off; off >>= 1)
            acc[k] += __shfl_xor_sync(0xffffffffu, acc[k], off);
    }
    if ((t & 31) == 0) {
        #pragma unroll
        for (int k = 0; k < NQ; ++k) sRed[t >> 5][k] = acc[k];
    }
    __syncthreads();
    if (t < NQ) {
        float s = 0.f;
        #pragma unroll
        for (int w = 0; w < NT / 32; ++w) s += sRed[w][t];
        out[b * NQ + t] = s;
    }
}

} // namespace

extern "C" void kernel_launch(void* const* d_in, const int* in_sizes, int n_in,
                              void* d_out, int out_size)
{
    (void)n_in; (void)out_size;
    // Disambiguate input order by element count: x is 4096*12, params is 6*12*3=216.
    const float* x;
    const float* params;
    if (in_sizes[0] == DEPTH * NQ * 3) {
        params = (const float*)d_in[0];
        x      = (const float*)d_in[1];
    } else {
        x      = (const float*)d_in[0];
        params = (const float*)d_in[1];
    }
    qsim_kernel<<<4096, NT>>>(x, params, (float*)d_out);
}

// round 2
// speedup vs baseline: 2.1775x; 2.1775x over previous
#include <cuda_runtime.h>

namespace {

constexpr int NQ     = 12;
constexpr int DEPTH  = 6;
constexpr int NSTATE = 1 << NQ;        // 4096
constexpr int NT     = 256;            // threads per CTA
constexpr int PT     = NSTATE / NT;    // 16 amplitudes per thread

// XOR swizzle: phys = idx ^ ((idx>>4)&0xF). Makes all three round access
// patterns (and the Gray-composed read) bank-conflict-free on float2 elements.
__device__ __forceinline__ int sw(int i) { return i ^ ((i >> 4) & 0xF); }

__device__ __forceinline__ float2 cmul(float2 a, float2 b) {
    float2 r;
    r.x = fmaf(a.x, b.x, -(a.y * b.y));
    r.y = fmaf(a.x, b.y, a.y * b.x);
    return r;
}

// (a,b) <- U @ (a,b) for a 2x2 complex gate
__device__ __forceinline__ void gate_pair(float2& a, float2& b,
                                          float2 u00, float2 u01,
                                          float2 u10, float2 u11)
{
    float2 na, nb;
    na.x = fmaf(u00.x, a.x, fmaf(-u00.y, a.y, fmaf(u01.x, b.x, -(u01.y * b.y))));
    na.y = fmaf(u00.x, a.y, fmaf( u00.y, a.x, fmaf(u01.x, b.y,   u01.y * b.x)));
    nb.x = fmaf(u10.x, a.x, fmaf(-u10.y, a.y, fmaf(u11.x, b.x, -(u11.y * b.y))));
    nb.y = fmaf(u10.x, a.y, fmaf( u10.y, a.x, fmaf(u11.x, b.y,   u11.y * b.x)));
    a = na; b = nb;
}

__global__ void __launch_bounds__(NT) qsim_kernel(const float* __restrict__ x,
                                                  const float* __restrict__ params,
                                                  float* __restrict__ out)
{
    __shared__ float2 sS[NSTATE];            // state, swizzled (32 KB)
    __shared__ float2 sU[DEPTH][NQ][4];      // fused 2x2 per (layer, qubit)
    __shared__ float  sRed[NT / 32][NQ];

    const int t = threadIdx.x;
    const int b = blockIdx.x;

    // ---- Build fused rotation matrices: U = RX(g) @ RZ(b) @ RY(a) ----
    // Layer 0 additionally absorbs the input-encoding RX: U0 = U @ RX(x_i).
    if (t < DEPTH * NQ) {
        const int d = t / NQ, i = t % NQ;
        const float* pp = params + (d * NQ + i) * 3;
        float sa, ca, sb, cb, sg, cg;
        sincosf(0.5f * pp[0], &sa, &ca);
        sincosf(0.5f * pp[1], &sb, &cb);
        sincosf(0.5f * pp[2], &sg, &cg);
        // M1 = RZ(beta) @ RY(alpha)
        float2 m00 = {  cb * ca, -sb * ca };
        float2 m01 = { -cb * sa,  sb * sa };
        float2 m10 = {  cb * sa,  sb * sa };
        float2 m11 = {  cb * ca,  sb * ca };
        // U = RX(gamma) @ M1
        float2 u00 = { cg * m00.x + sg * m10.y, cg * m00.y - sg * m10.x };
        float2 u01 = { cg * m01.x + sg * m11.y, cg * m01.y - sg * m11.x };
        float2 u10 = { sg * m00.y + cg * m10.x, -sg * m00.x + cg * m10.y };
        float2 u11 = { sg * m01.y + cg * m11.x, -sg * m01.x + cg * m11.y };
        if (d == 0) {
            float sx, cx;
            sincosf(0.5f * x[b * NQ + i], &sx, &cx);
            float2 v00 = { cx * u00.x + sx * u01.y,  cx * u00.y - sx * u01.x };
            float2 v01 = { sx * u00.y + cx * u01.x, -sx * u00.x + cx * u01.y };
            float2 v10 = { cx * u10.x + sx * u11.y,  cx * u10.y - sx * u11.x };
            float2 v11 = { sx * u10.y + cx * u11.x, -sx * u10.x + cx * u11.y };
            u00 = v00; u01 = v01; u10 = v10; u11 = v11;
        }
        sU[d][i][0] = u00; sU[d][i][1] = u01; sU[d][i][2] = u10; sU[d][i][3] = u11;
    }
    __syncthreads();

    // ---- Layer 0 on |0..0> is a product state: amp(idx) = prod_i U0[i][bit_i][col 0]
    // Pattern A: idx = (t<<4) | r  -> wires 0..7 from t bits [7:0], wires 8..11 from r.
    {
        float2 phi = { 1.f, 0.f };
        #pragma unroll
        for (int i = 0; i < 8; ++i) {
            int bit = (t >> (7 - i)) & 1;
            phi = cmul(phi, sU[0][i][bit ? 2 : 0]);
        }
        // wires 8,9 combos (r>>2) and wires 10,11 combos (r&3)
        float2 c89[4], cAB[4];
        #pragma unroll
        for (int h = 0; h < 4; ++h) {
            c89[h] = cmul(sU[0][8][(h >> 1) ? 2 : 0], sU[0][9][(h & 1) ? 2 : 0]);
            cAB[h] = cmul(sU[0][10][(h >> 1) ? 2 : 0], sU[0][11][(h & 1) ? 2 : 0]);
        }
        #pragma unroll
        for (int r = 0; r < PT; ++r) {
            float2 amp = cmul(phi, cmul(c89[r >> 2], cAB[r & 3]));
            sS[sw((t << 4) | r)] = amp;
        }
    }
    __syncthreads();

    // ---- Layers 1..5: three register rounds per layer.
    // Round C (wires 0..3, idx bits 11..8) reads with the PREVIOUS layer's
    // CNOT-chain Gray permutation folded in: new[i] = old[i ^ (i>>1)].
    for (int d = 1; d < DEPTH; ++d) {
        float2 s[PT];

        // ===== Round C: wires 0..3, with Gray gather =====
        #pragma unroll
        for (int r = 0; r < PT; ++r) {
            int dst = (r << 8) | t;
            int src = dst ^ (dst >> 1);
            s[r] = sS[sw(src)];
        }
        __syncthreads();               // everyone done reading old state
        #pragma unroll
        for (int j = 0; j < 4; ++j) {  // wire j -> idx bit 11-j -> local bit 3-j
            const int p = 3 - j;
            float2 u00 = sU[d][j][0], u01 = sU[d][j][1];
            float2 u10 = sU[d][j][2], u11 = sU[d][j][3];
            #pragma unroll
            for (int m = 0; m < 8; ++m) {
                int lo = m & ((1 << p) - 1);
                int i0 = ((m >> p) << (p + 1)) | lo;
                gate_pair(s[i0], s[i0 | (1 << p)], u00, u01, u10, u11);
            }
        }
        #pragma unroll
        for (int r = 0; r < PT; ++r) sS[sw((r << 8) | t)] = s[r];
        __syncthreads();

        // ===== Round B: wires 4..7 (idx bits 7..4) =====
        const int baseB = ((t >> 4) << 8) | (t & 15);
        #pragma unroll
        for (int r = 0; r < PT; ++r) s[r] = sS[sw(baseB | (r << 4))];
        __syncthreads();
        #pragma unroll
        for (int j = 0; j < 4; ++j) {  // wire 4+j -> idx bit 7-j -> local bit 3-j
            const int p = 3 - j;
            float2 u00 = sU[d][4 + j][0], u01 = sU[d][4 + j][1];
            float2 u10 = sU[d][4 + j][2], u11 = sU[d][4 + j][3];
            #pragma unroll
            for (int m = 0; m < 8; ++m) {
                int lo = m & ((1 << p) - 1);
                int i0 = ((m >> p) << (p + 1)) | lo;
                gate_pair(s[i0], s[i0 | (1 << p)], u00, u01, u10, u11);
            }
        }
        #pragma unroll
        for (int r = 0; r < PT; ++r) sS[sw(baseB | (r << 4))] = s[r];
        __syncthreads();

        // ===== Round A: wires 8..11 (idx bits 3..0) =====
        #pragma unroll
        for (int r = 0; r < PT; ++r) s[r] = sS[sw((t << 4) | r)];
        __syncthreads();
        #pragma unroll
        for (int j = 0; j < 4; ++j) {  // wire 8+j -> idx bit 3-j -> local bit 3-j
            const int p = 3 - j;
            float2 u00 = sU[d][8 + j][0], u01 = sU[d][8 + j][1];
            float2 u10 = sU[d][8 + j][2], u11 = sU[d][8 + j][3];
            #pragma unroll
            for (int m = 0; m < 8; ++m) {
                int lo = m & ((1 << p) - 1);
                int i0 = ((m >> p) << (p + 1)) | lo;
                gate_pair(s[i0], s[i0 | (1 << p)], u00, u01, u10, u11);
            }
        }
        #pragma unroll
        for (int r = 0; r < PT; ++r) sS[sw((t << 4) | r)] = s[r];
        __syncthreads();
    }

    // ---- Final: layer-5 CNOT chain folded into the reduction read (pattern C).
    // new_state[dst] = old[dst ^ (dst>>1)]; signs come from dst bits.
    float accLo[4];                                   // wires 0..3 (sign varies with r)
    #pragma unroll
    for (int k = 0; k < 4; ++k) accLo[k] = 0.f;
    float sumAll = 0.f;
    #pragma unroll
    for (int r = 0; r < PT; ++r) {
        int dst = (r << 8) | t;
        int src = dst ^ (dst >> 1);
        float2 a = sS[sw(src)];
        float pr = fmaf(a.x, a.x, a.y * a.y);
        sumAll += pr;
        #pragma unroll
        for (int k = 0; k < 4; ++k)
            accLo[k] += ((r >> (3 - k)) & 1) ? -pr : pr;
    }

    float acc[NQ];
    #pragma unroll
    for (int k = 0; k < 4; ++k) acc[k] = accLo[k];
    #pragma unroll
    for (int k = 4; k < NQ; ++k)                      // wires 4..11: sign from t bits
        acc[k] = ((t >> (11 - k)) & 1) ? -sumAll : sumAll;

    #pragma unroll
    for (int k = 0; k < NQ; ++k) {
        #pragma unroll
        for (int off = 16; off; off >>= 1)
            acc[k] += __shfl_xor_sync(0xffffffffu, acc[k], off);
    }
    if ((t & 31) == 0) {
        #pragma unroll
        for (int k = 0; k < NQ; ++k) sRed[t >> 5][k] = acc[k];
    }
    __syncthreads();
    if (t < NQ) {
        float sres = 0.f;
        #pragma unroll
        for (int w = 0; w < NT / 32; ++w) sres += sRed[w][t];
        out[b * NQ + t] = sres;
    }
}

} // namespace

extern "C" void kernel_launch(void* const* d_in, const int* in_sizes, int n_in,
                              void* d_out, int out_size)
{
    (void)n_in; (void)out_size;
    const float* x;
    const float* params;
    if (in_sizes[0] == DEPTH * NQ * 3) {
        params = (const float*)d_in[0];
        x      = (const float*)d_in[1];
    } else {
        x      = (const float*)d_in[0];
        params = (const float*)d_in[1];
    }
    qsim_kernel<<<4096, NT>>>(x, params, (float*)d_out);
}

// round 3
// speedup vs baseline: 2.7210x; 1.2496x over previous
#include <cuda_runtime.h>

namespace {

constexpr int NQ     = 12;
constexpr int DEPTH  = 6;
constexpr int NSTATE = 1 << NQ;        // 4096
constexpr int NT     = 256;            // threads per CTA
constexpr int PT     = NSTATE / NT;    // 16 amplitudes per thread

// XOR swizzle: conflict-free for all round patterns incl. the Gray gather.
__device__ __forceinline__ int sw(int i) { return i ^ ((i >> 4) & 0xF); }

__device__ __forceinline__ float2 cmul(float2 a, float2 b) {
    float2 r;
    r.x = fmaf(a.x, b.x, -(a.y * b.y));
    r.y = fmaf(a.x, b.y, a.y * b.x);
    return r;
}
__device__ __forceinline__ float2 cmulc(float2 a, float2 b) {  // a * conj(b)
    float2 r;
    r.x = fmaf(a.x, b.x,  a.y * b.y);
    r.y = fmaf(a.y, b.x, -(a.x * b.y));
    return r;
}

// real RY rotation on a pair: na = c*a - s*b ; nb = s*a + c*b   (8 FMA)
__device__ __forceinline__ void ry_pair(float2& a, float2& b, float c, float s) {
    float2 na, nb;
    na.x = fmaf(c, a.x, -(s * b.x));
    na.y = fmaf(c, a.y, -(s * b.y));
    nb.x = fmaf(s, a.x,   c * b.x);
    nb.y = fmaf(s, a.y,   c * b.y);
    a = na; b = nb;
}

__global__ void __launch_bounds__(NT) qsim_kernel(const float* __restrict__ x,
                                                  const float* __restrict__ params,
                                                  float* __restrict__ out)
{
    __shared__ float2 sS[NSTATE];          // state (32 KB), swizzled
    __shared__ float2 sU0[NQ][4];          // layer-0 full matrices (batch-dependent)
    __shared__ float  sC[DEPTH][NQ];       // RY cos per (layer, wire), d>=1
    __shared__ float  sSn[DEPTH][NQ];      // RY sin
    __shared__ float2 sB1[DEPTH][NQ];      // B-diag b1 per gate (b0 == 1 gauge), d>=1
    __shared__ float2 sA0[DEPTH][NQ];      // A-diag a0 (temp, for G0)
    __shared__ float2 sG [DEPTH][NQ];      // g = a1*conj(a0) per gate, used for d=1..4
    __shared__ float2 sG0[DEPTH];          // prod_i a0[d][i], d=1..4
    __shared__ float2 sPhi[DEPTH - 1][NT];      // per-layer per-thread fixed-bit phase
    __shared__ float2 sThi[DEPTH - 1][2][16];   // per-layer r-phase (x b7 coupling)
    __shared__ float  sRed[NT / 32][NQ];

    const int t = threadIdx.x;
    const int b = blockIdx.x;

    // ================= Stage A: build gates, decompose U = A * RY * B =======
    if (t < DEPTH * NQ) {
        const int d = t / NQ, i = t % NQ;
        const float* pp = params + (d * NQ + i) * 3;
        float sa, ca, sb, cb, sg, cg;
        sincosf(0.5f * pp[0], &sa, &ca);
        sincosf(0.5f * pp[1], &sb, &cb);
        sincosf(0.5f * pp[2], &sg, &cg);
        // M1 = RZ(beta) @ RY(alpha)
        float2 m00 = {  cb * ca, -sb * ca };
        float2 m01 = { -cb * sa,  sb * sa };
        float2 m10 = {  cb * sa,  sb * sa };
        float2 m11 = {  cb * ca,  sb * ca };
        // U = RX(gamma) @ M1
        float2 u00 = { cg * m00.x + sg * m10.y, cg * m00.y - sg * m10.x };
        float2 u01 = { cg * m01.x + sg * m11.y, cg * m01.y - sg * m11.x };
        float2 u10 = { sg * m00.y + cg * m10.x, -sg * m00.x + cg * m10.y };
        float2 u11 = { sg * m01.y + cg * m11.x, -sg * m01.x + cg * m11.y };
        if (d == 0) {
            // absorb input-encoding RX(x_i); keep layer 0 as full matrices
            float sx, cx;
            sincosf(0.5f * x[b * NQ + i], &sx, &cx);
            float2 v00 = { cx * u00.x + sx * u01.y,  cx * u00.y - sx * u01.x };
            float2 v01 = { sx * u00.y + cx * u01.x, -sx * u00.x + cx * u01.y };
            float2 v10 = { cx * u10.x + sx * u11.y,  cx * u10.y - sx * u11.x };
            float2 v11 = { sx * u10.y + cx * u11.x, -sx * u10.x + cx * u11.y };
            sU0[i][0] = v00; sU0[i][1] = v01; sU0[i][2] = v10; sU0[i][3] = v11;
        } else {
            // numerical ZYZ-style split: U = diag(a0,a1) * RY * diag(1,b1)
            float c = sqrtf(fmaf(u00.x, u00.x, u00.y * u00.y));
            float s = sqrtf(fmaf(u10.x, u10.x, u10.y * u10.y));
            float2 a0, a1, b1;
            if (s < 1e-12f) {
                float ic = 1.0f / c;
                a0 = { u00.x * ic, u00.y * ic };
                a1 = { u11.x * ic, u11.y * ic };
                b1 = { 1.f, 0.f };
            } else if (c < 1e-12f) {
                float is = 1.0f / s;
                a0 = { -u01.x * is, -u01.y * is };
                a1 = {  u10.x * is,  u10.y * is };
                b1 = { 1.f, 0.f };
            } else {
                float ic = 1.0f / c, is = 1.0f / s;
                a0 = { u00.x * ic, u00.y * ic };
                a1 = { u10.x * is, u10.y * is };
                float2 tb = cmulc(u11, a1);
                b1 = { tb.x * ic, tb.y * ic };
            }
            sC[d][i] = c;  sSn[d][i] = s;
            sB1[d][i] = b1;
            sA0[d][i] = a0;
            sG[d][i]  = cmulc(a1, a0);    // a1 * conj(a0)
        }
    }
    __syncthreads();

    // ================= Stage B: G0[d] = prod_i a0[d][i], d = 1..4 ===========
    if (t >= 1 && t <= 4) {
        float2 p = { 1.f, 0.f };
        #pragma unroll
        for (int i = 0; i < NQ; ++i) p = cmul(p, sA0[t][i]);
        sG0[t] = p;
    }
    __syncthreads();

    // ================= Stage C: diagonal tables =============================
    // D_d(dst) = [Lam^B_d * conj-propagated Lam^A_{d-1}] (dst) factorized as
    // Phi[t] * Thi[b7][r] with dst = (r<<8) | t.  A_5 is dropped (post-measure).
    #pragma unroll
    for (int k = 0; k < DEPTH - 1; ++k) {   // dd = k, layer d = k+1
        const int d = k + 1;
        float2 phi = (d >= 2) ? sG0[d - 1] : make_float2(1.f, 0.f);
        #pragma unroll
        for (int i = 4; i < NQ; ++i)
            if ((t >> (11 - i)) & 1) phi = cmul(phi, sB1[d][i]);
        if (d >= 2) {
            #pragma unroll
            for (int i = 5; i < NQ; ++i)
                if (((t >> (11 - i)) ^ (t >> (12 - i))) & 1)
                    phi = cmul(phi, sG[d - 1][i]);
        }
        sPhi[k][t] = phi;
    }
    if (t < (DEPTH - 1) * 32) {
        const int k = t / 32, e = (t >> 4) & 1, r = t & 15;
        const int d = k + 1;
        float2 T = { 1.f, 0.f };
        #pragma unroll
        for (int i = 0; i < 4; ++i)
            if ((r >> (3 - i)) & 1) T = cmul(T, sB1[d][i]);
        if (d >= 2) {
            int r0 = r & 1, r1 = (r >> 1) & 1, r2 = (r >> 2) & 1, r3 = (r >> 3) & 1;
            if (r3)      T = cmul(T, sG[d - 1][0]);
            if (r2 ^ r3) T = cmul(T, sG[d - 1][1]);
            if (r1 ^ r2) T = cmul(T, sG[d - 1][2]);
            if (r0 ^ r1) T = cmul(T, sG[d - 1][3]);
            if (e  ^ r0) T = cmul(T, sG[d - 1][4]);
        }
        sThi[k][e][r] = T;
    }
    __syncthreads();

    // ================= Layer 0 on |0..0>: product state =====================
    {
        float2 phi = { 1.f, 0.f };
        #pragma unroll
        for (int i = 0; i < 8; ++i) {
            int bit = (t >> (7 - i)) & 1;
            phi = cmul(phi, sU0[i][bit ? 2 : 0]);
        }
        float2 c89[4], cAB[4];
        #pragma unroll
        for (int h = 0; h < 4; ++h) {
            c89[h] = cmul(sU0[8][(h >> 1) ? 2 : 0], sU0[9][(h & 1) ? 2 : 0]);
            cAB[h] = cmul(sU0[10][(h >> 1) ? 2 : 0], sU0[11][(h & 1) ? 2 : 0]);
        }
        #pragma unroll
        for (int r = 0; r < PT; ++r)
            sS[sw((t << 4) | r)] = cmul(phi, cmul(c89[r >> 2], cAB[r & 3]));
    }
    __syncthreads();

    // ================= Layers 1..5 ==========================================
    for (int d = 1; d < DEPTH; ++d) {
        const int k = d - 1;
        float2 s[PT];

        // ---- Round C: Gray gather (prev layer's CNOT chain) + diagonal D_d
        #pragma unroll
        for (int r = 0; r < PT; ++r) {
            int dst = (r << 8) | t;
            int src = dst ^ (dst >> 1);
            s[r] = sS[sw(src)];
        }
        __syncthreads();
        {
            const float2 phi = sPhi[k][t];
            const float2* thi = sThi[k][(t >> 7) & 1];
            #pragma unroll
            for (int r = 0; r < PT; ++r) {
                float2 w = cmul(phi, thi[r]);
                s[r] = cmul(s[r], w);
            }
        }
        #pragma unroll
        for (int j = 0; j < 4; ++j) {           // wires 0..3 -> local bit 3-j
            const int p = 3 - j;
            const float c = sC[d][j], sn = sSn[d][j];
            #pragma unroll
            for (int m = 0; m < 8; ++m) {
                int lo = m & ((1 << p) - 1);
                int i0 = ((m >> p) << (p + 1)) | lo;
                ry_pair(s[i0], s[i0 | (1 << p)], c, sn);
            }
        }
        #pragma unroll
        for (int r = 0; r < PT; ++r) sS[sw((r << 8) | t)] = s[r];
        __syncthreads();

        // ---- Round B: wires 4..7 (per-thread addresses disjoint: no mid-sync)
        const int baseB = ((t >> 4) << 8) | (t & 15);
        #pragma unroll
        for (int r = 0; r < PT; ++r) s[r] = sS[sw(baseB | (r << 4))];
        #pragma unroll
        for (int j = 0; j < 4; ++j) {
            const int p = 3 - j;
            const float c = sC[d][4 + j], sn = sSn[d][4 + j];
            #pragma unroll
            for (int m = 0; m < 8; ++m) {
                int lo = m & ((1 << p) - 1);
                int i0 = ((m >> p) << (p + 1)) | lo;
                ry_pair(s[i0], s[i0 | (1 << p)], c, sn);
            }
        }
        #pragma unroll
        for (int r = 0; r < PT; ++r) sS[sw(baseB | (r << 4))] = s[r];
        __syncthreads();

        // ---- Round A: wires 8..11
        #pragma unroll
        for (int r = 0; r < PT; ++r) s[r] = sS[sw((t << 4) | r)];
        #pragma unroll
        for (int j = 0; j < 4; ++j) {
            const int p = 3 - j;
            const float c = sC[d][8 + j], sn = sSn[d][8 + j];
            #pragma unroll
            for (int m = 0; m < 8; ++m) {
                int lo = m & ((1 << p) - 1);
                int i0 = ((m >> p) << (p + 1)) | lo;
                ry_pair(s[i0], s[i0 | (1 << p)], c, sn);
            }
        }
        #pragma unroll
        for (int r = 0; r < PT; ++r) sS[sw((t << 4) | r)] = s[r];
        __syncthreads();
    }

    // ==== Final: layer-5 CNOT chain folded into the reduction read. ====
    // (Layer-5 A-diagonal dropped: unit phases don't change probabilities.)
    float accLo[4];
    #pragma unroll
    for (int q = 0; q < 4; ++q) accLo[q] = 0.f;
    float sumAll = 0.f;
    #pragma unroll
    for (int r = 0; r < PT; ++r) {
        int dst = (r << 8) | t;
        int src = dst ^ (dst >> 1);
        float2 a = sS[sw(src)];
        float pr = fmaf(a.x, a.x, a.y * a.y);
        sumAll += pr;
        #pragma unroll
        for (int q = 0; q < 4; ++q)
            accLo[q] += ((r >> (3 - q)) & 1) ? -pr : pr;
    }

    float acc[NQ];
    #pragma unroll
    for (int q = 0; q < 4; ++q) acc[q] = accLo[q];
    #pragma unroll
    for (int q = 4; q < NQ; ++q)
        acc[q] = ((t >> (11 - q)) & 1) ? -sumAll : sumAll;

    #pragma unroll
    for (int q = 0; q < NQ; ++q) {
        #pragma unroll
        for (int off = 16; off; off >>= 1)
            acc[q] += __shfl_xor_sync(0xffffffffu, acc[q], off);
    }
    if ((t & 31) == 0) {
        #pragma unroll
        for (int q = 0; q < NQ; ++q) sRed[t >> 5][q] = acc[q];
    }
    __syncthreads();
    if (t < NQ) {
        float sres = 0.f;
        #pragma unroll
        for (int w = 0; w < NT / 32; ++w) sres += sRed[w][t];
        out[b * NQ + t] = sres;
    }
}

} // namespace

extern "C" void kernel_launch(void* const* d_in, const int* in_sizes, int n_in,
                              void* d_out, int out_size)
{
    (void)n_in; (void)out_size;
    const float* x;
    const float* params;
    if (in_sizes[0] == DEPTH * NQ * 3) {
        params = (const float*)d_in[0];
        x      = (const float*)d_in[1];
    } else {
        x      = (const float*)d_in[0];
        params = (const float*)d_in[1];
    }
    qsim_kernel<<<4096, NT>>>(x, params, (float*)d_out);
}